// round 1
// baseline (speedup 1.0000x reference)
#include <cuda_runtime.h>
#include <cuda_bf16.h>

// Problem: n=1024, K=8 -> 8192 entries. Pairwise softplus loss between
// positive-labeled and negative-labeled entries:
//   total = sum_{a in pos, b in neg} log(1 + exp(v_b - v_a)) / (P*N)
//
// Restructuring:
//   exp(q - p) = exp(q) * exp(-p)           (precompute per-entry exps)
//   sum log(1 + t_i) = log prod (1 + t_i)   (product with exponent carry)
// Inner loop per pair: 1 FFMA + 1 FMUL; renorm (bit ops, ALU pipe) per 4 pairs.

#define CAP 8208   // 8192 entries + float4 padding (zero-filled)
#define NSEG 64    // negative-dimension segments per positive group

__device__ float  g_posExp[CAP];  // exp(-v) for positive entries, zero-padded
__device__ float  g_negExp[CAP];  // exp(+v) for negative entries, zero-padded
__device__ int    g_P;
__device__ int    g_N;
__device__ double g_acc;

// ---------------------------------------------------------------------------
__global__ void rul_init_kernel() {
    int i = blockIdx.x * blockDim.x + threadIdx.x;
    int stride = gridDim.x * blockDim.x;
    for (int j = i; j < CAP; j += stride) {
        g_posExp[j] = 0.0f;
        g_negExp[j] = 0.0f;
    }
    if (i == 0) {
        g_P = 0;
        g_N = 0;
        g_acc = 0.0;
    }
}

// ---------------------------------------------------------------------------
// Warp-aggregated compaction: build exp-transformed positive/negative lists.
__global__ void rul_compact_kernel(const float* __restrict__ pred,
                                   const int* __restrict__ label,
                                   int total) {
    int i = blockIdx.x * blockDim.x + threadIdx.x;
    float v = 0.0f;
    int yy = -1;
    if (i < total) {
        v = pred[i];
        yy = label[i];
    }
    bool isPos = (yy == 1);
    bool isNeg = (yy == 0);

    unsigned mp = __ballot_sync(0xFFFFFFFFu, isPos);
    unsigned mn = __ballot_sync(0xFFFFFFFFu, isNeg);
    unsigned lane = threadIdx.x & 31u;
    unsigned ltmask = (1u << lane) - 1u;

    int basep = 0, basen = 0;
    if (lane == 0) {
        if (mp) basep = atomicAdd(&g_P, __popc(mp));
        if (mn) basen = atomicAdd(&g_N, __popc(mn));
    }
    basep = __shfl_sync(0xFFFFFFFFu, basep, 0);
    basen = __shfl_sync(0xFFFFFFFFu, basen, 0);

    if (isPos) g_posExp[basep + __popc(mp & ltmask)] = expf(-v);
    if (isNeg) g_negExp[basen + __popc(mn & ltmask)] = expf(v);
}

// ---------------------------------------------------------------------------
// Extract binary exponent from m (m >= 1 always) into e, renormalize m to [1,2).
__device__ __forceinline__ void rul_renorm(float& m, int& e) {
    int b = __float_as_int(m);
    e += (b >> 23) - 127;
    m = __int_as_float((b & 0x007FFFFF) | 0x3F800000);
}

// One unit = (group of 4 positives) x (one segment of negatives).
// Each thread runs 4 independent product chains sharing each negative float4.
__global__ void rul_pair_kernel() {
    int P = g_P;
    int N = g_N;
    int G4  = (P + 3) >> 2;                 // positive groups of 4
    int nf4 = (N + 3) >> 2;                 // negative float4 count
    int len = (nf4 + NSEG - 1) / NSEG;      // float4s per segment
    int units = G4 * NSEG;

    const float4* __restrict__ negf4 = reinterpret_cast<const float4*>(g_negExp);
    const float4* __restrict__ posf4 = reinterpret_cast<const float4*>(g_posExp);

    float threadSum = 0.0f;
    int tid = blockIdx.x * blockDim.x + threadIdx.x;
    int stride = gridDim.x * blockDim.x;

    for (int u = tid; u < units; u += stride) {
        int seg = u / G4;        // consecutive threads share seg -> broadcast LDS/L1
        int pg  = u - seg * G4;  // consecutive threads -> coalesced positive loads

        float4 F = posf4[pg];
        int j0 = seg * len;
        int j1 = min(j0 + len, nf4);

        float m0 = 1.0f, m1 = 1.0f, m2 = 1.0f, m3 = 1.0f;
        int   e0 = 0,    e1 = 0,    e2 = 0,    e3 = 0;

        for (int j = j0; j < j1; ++j) {
            float4 q = negf4[j];
            {
                float t0 = fmaf(q.x, F.x, 1.0f), t1 = fmaf(q.y, F.x, 1.0f);
                float t2 = fmaf(q.z, F.x, 1.0f), t3 = fmaf(q.w, F.x, 1.0f);
                m0 *= (t0 * t1) * (t2 * t3);
                rul_renorm(m0, e0);
            }
            {
                float t0 = fmaf(q.x, F.y, 1.0f), t1 = fmaf(q.y, F.y, 1.0f);
                float t2 = fmaf(q.z, F.y, 1.0f), t3 = fmaf(q.w, F.y, 1.0f);
                m1 *= (t0 * t1) * (t2 * t3);
                rul_renorm(m1, e1);
            }
            {
                float t0 = fmaf(q.x, F.z, 1.0f), t1 = fmaf(q.y, F.z, 1.0f);
                float t2 = fmaf(q.z, F.z, 1.0f), t3 = fmaf(q.w, F.z, 1.0f);
                m2 *= (t0 * t1) * (t2 * t3);
                rul_renorm(m2, e2);
            }
            {
                float t0 = fmaf(q.x, F.w, 1.0f), t1 = fmaf(q.y, F.w, 1.0f);
                float t2 = fmaf(q.z, F.w, 1.0f), t3 = fmaf(q.w, F.w, 1.0f);
                m3 *= (t0 * t1) * (t2 * t3);
                rul_renorm(m3, e3);
            }
        }

        threadSum += (float)(e0 + e1 + e2 + e3) * 0.6931471805599453f
                   + __logf(m0) + __logf(m1) + __logf(m2) + __logf(m3);
    }

    // Block reduction, one double atomic per block.
    __shared__ float red[256];
    red[threadIdx.x] = threadSum;
    __syncthreads();
#pragma unroll
    for (int s = 128; s > 0; s >>= 1) {
        if (threadIdx.x < s) red[threadIdx.x] += red[threadIdx.x + s];
        __syncthreads();
    }
    if (threadIdx.x == 0) atomicAdd(&g_acc, (double)red[0]);
}

// ---------------------------------------------------------------------------
__global__ void rul_finalize_kernel(float* __restrict__ out) {
    double denom = (double)g_P * (double)g_N;
    out[0] = (float)(g_acc / denom);
}

// ---------------------------------------------------------------------------
extern "C" void kernel_launch(void* const* d_in, const int* in_sizes, int n_in,
                              void* d_out, int out_size) {
    const float* pred  = (const float*)d_in[0];
    const int*   label = (const int*)d_in[1];
    int total = in_sizes[0];   // n*K = 8192

    rul_init_kernel<<<16, 256>>>();
    rul_compact_kernel<<<(total + 255) / 256, 256>>>(pred, label, total);
    rul_pair_kernel<<<296, 256>>>();
    rul_finalize_kernel<<<1, 1>>>((float*)d_out);
}